// round 15
// baseline (speedup 1.0000x reference)
#include <cuda_runtime.h>
#include <cuda_bf16.h>
#include <cuda_fp16.h>
#include <math.h>
#include <stdint.h>

#define NNODES 50000
#define NEDGES 800000
#define FDIM   256          // H*C
#define TOTE   (NEDGES + NNODES)

// ---------------- scratch (static device globals; no allocation) ----------------
__device__ __half   g_A16[(size_t)NNODES * FDIM];   // fp16 A operand
__device__ uint8_t  g_bufH8[(size_t)NNODES * FDIM]; // layer-1 h in fp8 e4m3 (agg0 gather src)
__device__ __half   g_bufH2[(size_t)NNODES * FDIM]; // layer-2 h in fp16 (agg1 gather src)
__device__ float g_asrcv[NNODES * 4];               // layer-1 scores
__device__ float g_adstv[NNODES * 4];
__device__ float g_asrcv2[NNODES * 4];              // layer-2 scores
__device__ float g_adstv2[NNODES * 4];
__device__ int   g_deg[NNODES];                     // invariant: zero at call entry
__device__ int2  g_rowseg[NNODES];                  // (start, end) of node's segment
__device__ int   g_cursor[NNODES];
__device__ int   g_srclist[TOTE];
__device__ int   g_dstlist[TOTE];
__device__ __half g_pedge[(size_t)TOTE * 4];        // per-(edge,head) softmax numerators
__device__ int   g_allocCtr;
__device__ __half g_B16_1[32768];       // layer-1 weights fp16 [128][256]
__device__ __half g_B16_2[65536];       // layer-2 weights fp16 [256][256]
__device__ float g_bnA[512];
__device__ float g_bnB[512];
__device__ float g_gmax[8];             // per-head global max of asrc (layer slots)

// ---------------- PTX helpers ----------------
__device__ __forceinline__ uint32_t s2u(const void* p) {
    uint32_t a;
    asm("{ .reg .u64 t; cvta.to.shared.u64 t, %1; cvt.u32.u64 %0, t; }" : "=r"(a) : "l"(p));
    return a;
}

__device__ __forceinline__ void ldsm4(uint32_t* r, uint32_t addr) {
    asm volatile("ldmatrix.sync.aligned.m8n8.x4.shared.b16 {%0,%1,%2,%3}, [%4];"
                 : "=r"(r[0]), "=r"(r[1]), "=r"(r[2]), "=r"(r[3]) : "r"(addr));
}

__device__ __forceinline__ void ldsm4t(uint32_t* r, uint32_t addr) {
    asm volatile("ldmatrix.sync.aligned.m8n8.x4.trans.shared.b16 {%0,%1,%2,%3}, [%4];"
                 : "=r"(r[0]), "=r"(r[1]), "=r"(r[2]), "=r"(r[3]) : "r"(addr));
}

__device__ __forceinline__ void mma16816h(float* d, const uint32_t* a, const uint32_t* b) {
    asm volatile("mma.sync.aligned.m16n8k16.row.col.f32.f16.f16.f32 "
                 "{%0,%1,%2,%3}, {%4,%5,%6,%7}, {%8,%9}, {%0,%1,%2,%3};"
                 : "+f"(d[0]), "+f"(d[1]), "+f"(d[2]), "+f"(d[3])
                 : "r"(a[0]), "r"(a[1]), "r"(a[2]), "r"(a[3]), "r"(b[0]), "r"(b[1]));
}

__device__ __forceinline__ void cpasync16(uint32_t dst, const void* src, int sz) {
    asm volatile("cp.async.cg.shared.global [%0], [%1], 16, %2;"
                 :: "r"(dst), "l"(src), "r"(sz) : "memory");
}

__device__ __forceinline__ float lrelu(float e) {
    return (e > 0.f) ? e : 0.2f * e;
}

__device__ __forceinline__ void atomicMaxF(float* a, float v) {
    if (v >= 0.f) atomicMax((int*)a, __float_as_int(v));
    else atomicMin((unsigned int*)a, __float_as_uint(v));
}

__device__ __forceinline__ uint16_t pack_e4m3x2(float lo, float hi) {
    uint16_t p;
    asm("cvt.rn.satfinite.e4m3x2.f32 %0, %1, %2;" : "=h"(p) : "f"(hi), "f"(lo));
    return p;
}

__device__ __forceinline__ float2 fp8x2f(uint32_t v) {
    uint32_t h2;
    asm("cvt.rn.f16x2.e4m3x2 %0, %1;" : "=r"(h2) : "h"((uint16_t)v));
    return __half22float2(*(__half2*)&h2);
}

// ---------------- CSR build ----------------
__global__ void k_prepB2count(const float* __restrict__ W2, __half* __restrict__ B2,
                              const int* __restrict__ ei) {
    int b = blockIdx.x, t = threadIdx.x;
    if (b < 256) {
        int i = b * 256 + t;
        B2[i] = __float2half_rn(W2[i]);
    } else {
        int i = (b - 256) * 256 + t;
        if (i == 0) g_allocCtr = 0;
        if (i < NEDGES) atomicAdd(&g_deg[ei[NEDGES + i]], 1);
    }
}

__global__ void k_alloc() {
    __shared__ int s[256];
    __shared__ int base;
    int t = threadIdx.x;
    int i = blockIdx.x * 256 + t;
    int len = 0;
    if (i < NNODES) {
        len = g_deg[i] + 1;   // +1 self loop
        g_deg[i] = 0;         // restore zero invariant
    }
    s[t] = len;
    __syncthreads();
    for (int off = 1; off < 256; off <<= 1) {
        int u = (t >= off) ? s[t - off] : 0;
        __syncthreads();
        s[t] += u;
        __syncthreads();
    }
    if (t == 255) base = atomicAdd(&g_allocCtr, s[255]);
    __syncthreads();
    if (i < NNODES) {
        int r = base + s[t] - len;
        g_rowseg[i] = make_int2(r, r + len);
        g_srclist[r] = i;      // self loop first
        g_dstlist[r] = i;
        g_cursor[i] = r + 1;
    }
}

__global__ void k_fill(const int* __restrict__ ei) {
    int i = blockIdx.x * blockDim.x + threadIdx.x;
    if (i < NEDGES) {
        int s = ei[i];
        int d = ei[NEDGES + i];
        int pos = atomicAdd(&g_cursor[d], 1);
        g_srclist[pos] = s;
        g_dstlist[pos] = d;
    }
}

__global__ void k_sort() {
    int n = blockIdx.x * blockDim.x + threadIdx.x;
    if (n >= NNODES) return;
    int2 rs = g_rowseg[n];
    int beg = rs.x + 1;
    int end = rs.y;
    int len = end - beg;
    if (len <= 1) return;
    if (len <= 56) {
        int buf[56];
        for (int i = 0; i < len; i++) buf[i] = g_srclist[beg + i];
        for (int i = 1; i < len; i++) {
            int key = buf[i];
            int j = i - 1;
            while (j >= 0 && buf[j] > key) {
                buf[j + 1] = buf[j];
                j--;
            }
            buf[j + 1] = key;
        }
        for (int i = 0; i < len; i++) g_srclist[beg + i] = buf[i];
    } else {
        for (int i = beg + 1; i < end; i++) {
            int key = g_srclist[i];
            int j = i - 1;
            while (j >= beg && g_srclist[j] > key) {
                g_srclist[j + 1] = g_srclist[j];
                j--;
            }
            g_srclist[j + 1] = key;
        }
    }
}

// ---------------- fused prep ----------------
#define PREPA_BLKS 25000     // 50000*128/256
__global__ void k_prepAll(const float* __restrict__ X,
                          const float* __restrict__ W1, __half* __restrict__ B1,
                          const float* __restrict__ b1, const float* __restrict__ g1,
                          const float* __restrict__ be1, const float* __restrict__ m1,
                          const float* __restrict__ v1,
                          const float* __restrict__ b2, const float* __restrict__ g2,
                          const float* __restrict__ be2, const float* __restrict__ m2,
                          const float* __restrict__ v2) {
    int b = blockIdx.x, t = threadIdx.x;
    if (b < PREPA_BLKS) {
        int i = b * 256 + t;
        g_A16[i] = __float2half_rn(X[i]);
    } else if (b < PREPA_BLKS + 128) {
        int i = (b - PREPA_BLKS) * 256 + t;
        B1[i] = __float2half_rn(W1[i]);
    } else {
        for (int i = t; i < 512; i += 256) {
            if (i < 256) {
                float s = g1[i] * rsqrtf(v1[i] + 1e-5f);
                g_bnA[i] = s;
                g_bnB[i] = (b1[i] - m1[i]) * s + be1[i];
            } else {
                int j = i - 256;
                float s = g2[j] * rsqrtf(v2[j] + 1e-5f);
                g_bnA[i] = s;
                g_bnB[i] = (b2[j] - m2[j]) * s + be2[j];
            }
        }
        if (t < 8) g_gmax[t] = -1e30f;
    }
}

// ---------------- per-edge softmax numerators (edge-parallel, pipelined) ----------------
// p[k][h] = exp(lrelu(asrc[s][h]+adst[d][h]) - lrelu(gmax[h]+adst[d][h]))
// Softmax is invariant to the per-dst shift; the shift bounds all numerators <= 1.
__global__ void k_edgep(const float* __restrict__ scs, const float* __restrict__ scd,
                        const float* __restrict__ gmax) {
    int k = blockIdx.x * 256 + threadIdx.x;
    if (k >= TOTE) return;
    int s = g_srclist[k];
    int d = g_dstlist[k];
    float4 av = *(const float4*)(scs + s * 4);
    float4 dv = *(const float4*)(scd + d * 4);
    float p0 = __expf(lrelu(av.x + dv.x) - lrelu(gmax[0] + dv.x));
    float p1 = __expf(lrelu(av.y + dv.y) - lrelu(gmax[1] + dv.y));
    float p2 = __expf(lrelu(av.z + dv.z) - lrelu(gmax[2] + dv.z));
    float p3 = __expf(lrelu(av.w + dv.w) - lrelu(gmax[3] + dv.w));
    __half2* o = (__half2*)(g_pedge + (size_t)k * 4);
    o[0] = __floats2half2_rn(p0, p1);
    o[1] = __floats2half2_rn(p2, p3);
}

// ---------------- fp16 tensor-core GEMM ----------------
#define GSTAGE 27136
template <int FP8OUT>
__global__ void __launch_bounds__(512) k_gemm_mma(const __half* __restrict__ Ap,
                                                  const __half* __restrict__ Bp,
                                                  void* __restrict__ Hout, int K,
                                                  const float* __restrict__ Asrc,
                                                  const float* __restrict__ Adst,
                                                  float* __restrict__ osrc,
                                                  float* __restrict__ odst,
                                                  float* __restrict__ gmax) {
    extern __shared__ char sm[];
    uint32_t sbase = s2u(sm);

    int tid = threadIdx.x;
    int lane = tid & 31, w = tid >> 5;
    int wm = w & 3, wn = w >> 2;
    int by = blockIdx.x;
    int nch = K >> 5;

    int ar = tid >> 2, ac = tid & 3;
    int agr = by * 128 + ar;
    int asz = (agr < NNODES) ? 16 : 0;
    int agc = (agr < NNODES) ? agr : 0;
    const char* gA = (const char*)(Ap + (size_t)agc * K + ac * 8);
    uint32_t dA = (uint32_t)(ar * 80 + ac * 16);

    float acc[2][8][4];
#pragma unroll
    for (int i = 0; i < 2; i++)
#pragma unroll
        for (int j = 0; j < 8; j++)
#pragma unroll
            for (int q = 0; q < 4; q++) acc[i][j][q] = 0.f;

#define ISSUE(kc, s) do {                                                          \
        uint32_t so = sbase + (s) * GSTAGE;                                        \
        cpasync16(so + dA, gA + (size_t)(kc) * 64, asz);                           \
        _Pragma("unroll")                                                          \
        for (int i = 0; i < 2; i++) {                                              \
            int p = tid + 512 * i;                                                 \
            int rr = p >> 5, c2 = p & 31;                                          \
            size_t go = (size_t)((kc) * 32 + rr) * 256 + c2 * 8;                   \
            cpasync16(so + 10240 + rr * 528 + c2 * 16, (const char*)(Bp + go), 16);\
        }                                                                          \
        asm volatile("cp.async.commit_group;" ::: "memory");                       \
    } while (0)

    ISSUE(0, 0);

    for (int kc = 0; kc < nch; kc++) {
        int s = kc & 1;
        if (kc + 1 < nch) {
            ISSUE(kc + 1, (kc + 1) & 1);
            asm volatile("cp.async.wait_group 1;" ::: "memory");
        } else {
            asm volatile("cp.async.wait_group 0;" ::: "memory");
        }
        __syncthreads();

        uint32_t aoff = sbase + s * GSTAGE;
        uint32_t boff = aoff + 10240;
#pragma unroll
        for (int ks = 0; ks < 2; ks++) {
            uint32_t av[2][4], bv[4][4];
#pragma unroll
            for (int mt = 0; mt < 2; mt++) {
                int row = wm * 32 + mt * 16 + (lane & 15);
                ldsm4(av[mt], aoff + row * 80 + ks * 32 + (lane >> 4) * 16);
            }
#pragma unroll
            for (int nt = 0; nt < 4; nt++) {
                int row = ks * 16 + (lane & 15);
                ldsm4t(bv[nt], boff + row * 528 + (wn * 64 + nt * 16) * 2 + (lane >> 4) * 16);
            }
#pragma unroll
            for (int mt = 0; mt < 2; mt++)
#pragma unroll
                for (int nt = 0; nt < 4; nt++)
#pragma unroll
                    for (int h = 0; h < 2; h++)
                        mma16816h(acc[mt][nt * 2 + h], av[mt], &bv[nt][h * 2]);
        }
        __syncthreads();
    }

    // ---- epilogue ----
    int head = wn;
    float wmax = -1e30f;
#pragma unroll
    for (int mt = 0; mt < 2; mt++) {
        int r0 = by * 128 + wm * 32 + mt * 16 + (lane >> 2);
        float ps0 = 0.f, ps1 = 0.f, pd0 = 0.f, pd1 = 0.f;
#pragma unroll
        for (int nt = 0; nt < 8; nt++) {
            int cc = wn * 64 + nt * 8 + (lane & 3) * 2;
            float as0 = Asrc[cc], as1v = Asrc[cc + 1];
            float ad0 = Adst[cc], ad1v = Adst[cc + 1];
            ps0 += acc[mt][nt][0] * as0 + acc[mt][nt][1] * as1v;
            pd0 += acc[mt][nt][0] * ad0 + acc[mt][nt][1] * ad1v;
            ps1 += acc[mt][nt][2] * as0 + acc[mt][nt][3] * as1v;
            pd1 += acc[mt][nt][2] * ad0 + acc[mt][nt][3] * ad1v;
            if (FP8OUT) {
                uint8_t* H8 = (uint8_t*)Hout;
                if (r0 < NNODES)
                    *(uint16_t*)(H8 + (size_t)r0 * FDIM + cc) =
                        pack_e4m3x2(acc[mt][nt][0], acc[mt][nt][1]);
                if (r0 + 8 < NNODES)
                    *(uint16_t*)(H8 + (size_t)(r0 + 8) * FDIM + cc) =
                        pack_e4m3x2(acc[mt][nt][2], acc[mt][nt][3]);
            } else {
                __half* H = (__half*)Hout;
                if (r0 < NNODES)
                    *(__half2*)(H + (size_t)r0 * FDIM + cc) =
                        __floats2half2_rn(acc[mt][nt][0], acc[mt][nt][1]);
                if (r0 + 8 < NNODES)
                    *(__half2*)(H + (size_t)(r0 + 8) * FDIM + cc) =
                        __floats2half2_rn(acc[mt][nt][2], acc[mt][nt][3]);
            }
        }
#pragma unroll
        for (int off = 1; off <= 2; off <<= 1) {
            ps0 += __shfl_xor_sync(0xffffffffu, ps0, off);
            ps1 += __shfl_xor_sync(0xffffffffu, ps1, off);
            pd0 += __shfl_xor_sync(0xffffffffu, pd0, off);
            pd1 += __shfl_xor_sync(0xffffffffu, pd1, off);
        }
        wmax = fmaxf(wmax, fmaxf(ps0, ps1));
        if ((lane & 3) == 0) {
            if (r0 < NNODES) {
                osrc[r0 * 4 + head] = ps0;
                odst[r0 * 4 + head] = pd0;
            }
            if (r0 + 8 < NNODES) {
                osrc[(r0 + 8) * 4 + head] = ps1;
                odst[(r0 + 8) * 4 + head] = pd1;
            }
        }
    }
#pragma unroll
    for (int off = 4; off <= 16; off <<= 1)
        wmax = fmaxf(wmax, __shfl_xor_sync(0xffffffffu, wmax, off));
    if (lane == 0) atomicMaxF(&gmax[head], wmax);
}

// ---------------- GAT aggregation: gather + precomputed p ----------------
// MODE 0: fp8 gather, write fp16 A operand. MODE 1: fp16 gather, log_softmax + fp32 out.
template <int MODE>
__global__ void __launch_bounds__(256) k_agg(const void* __restrict__ Xv,
                      const float* __restrict__ bnA,
                      const float* __restrict__ bnB,
                      float* __restrict__ OUT) {
    int gwarp = (blockIdx.x * blockDim.x + threadIdx.x) >> 5;
    int lane = threadIdx.x & 31;
    if (gwarp >= NNODES) return;
    int n = gwarp;
    int ch0 = lane * 8;
    int hl = lane >> 3;

    const int* __restrict__ lst = g_srclist;
    const __half* __restrict__ pe = g_pedge;

    int2 rs = g_rowseg[n];
    int r0 = rs.x, r1 = rs.y;

    float dsum = 0.f;
    float acc[8];
#pragma unroll
    for (int j = 0; j < 8; j++) acc[j] = 0.f;

    int k = r0;
    if (MODE == 0) {
        const uint8_t* X8 = (const uint8_t*)Xv;
        for (; k + 3 < r1; k += 4) {
            int s0 = lst[k], s1 = lst[k + 1], s2 = lst[k + 2], s3 = lst[k + 3];
            uint2 ra = *(const uint2*)(X8 + (size_t)s0 * FDIM + ch0);
            uint2 rb = *(const uint2*)(X8 + (size_t)s1 * FDIM + ch0);
            uint2 rc = *(const uint2*)(X8 + (size_t)s2 * FDIM + ch0);
            uint2 rd = *(const uint2*)(X8 + (size_t)s3 * FDIM + ch0);
            float p0 = __half2float(pe[(size_t)(k + 0) * 4 + hl]);
            float p1 = __half2float(pe[(size_t)(k + 1) * 4 + hl]);
            float p2 = __half2float(pe[(size_t)(k + 2) * 4 + hl]);
            float p3 = __half2float(pe[(size_t)(k + 3) * 4 + hl]);
            dsum += (p0 + p1) + (p2 + p3);
            float2 a0 = fp8x2f(ra.x), a1 = fp8x2f(ra.x >> 16), a2 = fp8x2f(ra.y), a3 = fp8x2f(ra.y >> 16);
            float2 b0 = fp8x2f(rb.x), b1 = fp8x2f(rb.x >> 16), b2 = fp8x2f(rb.y), b3 = fp8x2f(rb.y >> 16);
            float2 c0 = fp8x2f(rc.x), c1 = fp8x2f(rc.x >> 16), c2 = fp8x2f(rc.y), c3 = fp8x2f(rc.y >> 16);
            float2 d0 = fp8x2f(rd.x), d1 = fp8x2f(rd.x >> 16), d2 = fp8x2f(rd.y), d3 = fp8x2f(rd.y >> 16);
            acc[0] += (p0 * a0.x + p1 * b0.x) + (p2 * c0.x + p3 * d0.x);
            acc[1] += (p0 * a0.y + p1 * b0.y) + (p2 * c0.y + p3 * d0.y);
            acc[2] += (p0 * a1.x + p1 * b1.x) + (p2 * c1.x + p3 * d1.x);
            acc[3] += (p0 * a1.y + p1 * b1.y) + (p2 * c1.y + p3 * d1.y);
            acc[4] += (p0 * a2.x + p1 * b2.x) + (p2 * c2.x + p3 * d2.x);
            acc[5] += (p0 * a2.y + p1 * b2.y) + (p2 * c2.y + p3 * d2.y);
            acc[6] += (p0 * a3.x + p1 * b3.x) + (p2 * c3.x + p3 * d3.x);
            acc[7] += (p0 * a3.y + p1 * b3.y) + (p2 * c3.y + p3 * d3.y);
        }
        for (; k < r1; k++) {
            int s0 = lst[k];
            uint2 ra = *(const uint2*)(X8 + (size_t)s0 * FDIM + ch0);
            float p0 = __half2float(pe[(size_t)k * 4 + hl]);
            dsum += p0;
            float2 a0 = fp8x2f(ra.x), a1 = fp8x2f(ra.x >> 16), a2 = fp8x2f(ra.y), a3 = fp8x2f(ra.y >> 16);
            acc[0] += p0 * a0.x;
            acc[1] += p0 * a0.y;
            acc[2] += p0 * a1.x;
            acc[3] += p0 * a1.y;
            acc[4] += p0 * a2.x;
            acc[5] += p0 * a2.y;
            acc[6] += p0 * a3.x;
            acc[7] += p0 * a3.y;
        }
    } else {
        const __half* X = (const __half*)Xv;
        for (; k + 3 < r1; k += 4) {
            int s0 = lst[k], s1 = lst[k + 1], s2 = lst[k + 2], s3 = lst[k + 3];
            uint4 ra = *(const uint4*)(X + (size_t)s0 * FDIM + ch0);
            uint4 rb = *(const uint4*)(X + (size_t)s1 * FDIM + ch0);
            uint4 rc = *(const uint4*)(X + (size_t)s2 * FDIM + ch0);
            uint4 rd = *(const uint4*)(X + (size_t)s3 * FDIM + ch0);
            float p0 = __half2float(pe[(size_t)(k + 0) * 4 + hl]);
            float p1 = __half2float(pe[(size_t)(k + 1) * 4 + hl]);
            float p2 = __half2float(pe[(size_t)(k + 2) * 4 + hl]);
            float p3 = __half2float(pe[(size_t)(k + 3) * 4 + hl]);
            dsum += (p0 + p1) + (p2 + p3);
            float2 a0 = __half22float2(*(__half2*)&ra.x);
            float2 a1 = __half22float2(*(__half2*)&ra.y);
            float2 a2 = __half22float2(*(__half2*)&ra.z);
            float2 a3 = __half22float2(*(__half2*)&ra.w);
            float2 b0 = __half22float2(*(__half2*)&rb.x);
            float2 b1 = __half22float2(*(__half2*)&rb.y);
            float2 b2 = __half22float2(*(__half2*)&rb.z);
            float2 b3 = __half22float2(*(__half2*)&rb.w);
            float2 c0 = __half22float2(*(__half2*)&rc.x);
            float2 c1 = __half22float2(*(__half2*)&rc.y);
            float2 c2 = __half22float2(*(__half2*)&rc.z);
            float2 c3 = __half22float2(*(__half2*)&rc.w);
            float2 d0 = __half22float2(*(__half2*)&rd.x);
            float2 d1 = __half22float2(*(__half2*)&rd.y);
            float2 d2 = __half22float2(*(__half2*)&rd.z);
            float2 d3 = __half22float2(*(__half2*)&rd.w);
            acc[0] += (p0 * a0.x + p1 * b0.x) + (p2 * c0.x + p3 * d0.x);
            acc[1] += (p0 * a0.y + p1 * b0.y) + (p2 * c0.y + p3 * d0.y);
            acc[2] += (p0 * a1.x + p1 * b1.x) + (p2 * c1.x + p3 * d1.x);
            acc[3] += (p0 * a1.y + p1 * b1.y) + (p2 * c1.y + p3 * d1.y);
            acc[4] += (p0 * a2.x + p1 * b2.x) + (p2 * c2.x + p3 * d2.x);
            acc[5] += (p0 * a2.y + p1 * b2.y) + (p2 * c2.y + p3 * d2.y);
            acc[6] += (p0 * a3.x + p1 * b3.x) + (p2 * c3.x + p3 * d3.x);
            acc[7] += (p0 * a3.y + p1 * b3.y) + (p2 * c3.y + p3 * d3.y);
        }
        for (; k < r1; k++) {
            int s0 = lst[k];
            uint4 ra = *(const uint4*)(X + (size_t)s0 * FDIM + ch0);
            float p0 = __half2float(pe[(size_t)k * 4 + hl]);
            dsum += p0;
            float2 a0 = __half22float2(*(__half2*)&ra.x);
            float2 a1 = __half22float2(*(__half2*)&ra.y);
            float2 a2 = __half22float2(*(__half2*)&ra.z);
            float2 a3 = __half22float2(*(__half2*)&ra.w);
            acc[0] += p0 * a0.x;
            acc[1] += p0 * a0.y;
            acc[2] += p0 * a1.x;
            acc[3] += p0 * a1.y;
            acc[4] += p0 * a2.x;
            acc[5] += p0 * a2.y;
            acc[6] += p0 * a3.x;
            acc[7] += p0 * a3.y;
        }
    }

    float inv = 1.f / (dsum + 1e-16f);
    float ov[8];
#pragma unroll
    for (int j = 0; j < 8; j++) {
        int ch = ch0 + j;
        ov[j] = fmaxf(fmaf(acc[j] * inv, bnA[ch], bnB[ch]), 0.f);
    }

    if (MODE == 0) {
        uint4 hv;
        *(__half2*)&hv.x = __floats2half2_rn(ov[0], ov[1]);
        *(__half2*)&hv.y = __floats2half2_rn(ov[2], ov[3]);
        *(__half2*)&hv.z = __floats2half2_rn(ov[4], ov[5]);
        *(__half2*)&hv.w = __floats2half2_rn(ov[6], ov[7]);
        *(uint4*)(g_A16 + (size_t)n * FDIM + ch0) = hv;
    } else {
        float m2 = ov[0];
#pragma unroll
        for (int j = 1; j < 8; j++) m2 = fmaxf(m2, ov[j]);
#pragma unroll
        for (int off = 16; off > 0; off >>= 1) m2 = fmaxf(m2, __shfl_xor_sync(0xffffffffu, m2, off));
        float se = 0.f;
#pragma unroll
        for (int j = 0; j < 8; j++) se += __expf(ov[j] - m2);
#pragma unroll
        for (int off = 16; off > 0; off >>= 1) se += __shfl_xor_sync(0xffffffffu, se, off);
        float lse = m2 + logf(se);
        float4* op = (float4*)(OUT + (size_t)n * FDIM + ch0);
        op[0] = make_float4(ov[0] - lse, ov[1] - lse, ov[2] - lse, ov[3] - lse);
        op[1] = make_float4(ov[4] - lse, ov[5] - lse, ov[6] - lse, ov[7] - lse);
    }
}

// ---------------- launch ----------------
extern "C" void kernel_launch(void* const* d_in, const int* in_sizes, int n_in,
                              void* d_out, int out_size) {
    const float* x    = (const float*)d_in[0];
    const int*   ei   = (const int*)d_in[1];
    const float* W1   = (const float*)d_in[2];
    const float* as1  = (const float*)d_in[3];
    const float* ad1  = (const float*)d_in[4];
    const float* b1   = (const float*)d_in[5];
    const float* gam1 = (const float*)d_in[6];
    const float* be1  = (const float*)d_in[7];
    const float* m1   = (const float*)d_in[8];
    const float* v1   = (const float*)d_in[9];
    const float* W2   = (const float*)d_in[10];
    const float* as2  = (const float*)d_in[11];
    const float* ad2  = (const float*)d_in[12];
    const float* b2   = (const float*)d_in[13];
    const float* gam2 = (const float*)d_in[14];
    const float* be2  = (const float*)d_in[15];
    const float* m2   = (const float*)d_in[16];
    const float* v2   = (const float*)d_in[17];
    float* out = (float*)d_out;

    __half *A16, *B1, *B2, *bufH2;
    uint8_t *bufH8;
    float *bnA, *bnB, *gmax, *sc1s, *sc1d, *sc2s, *sc2d;
    cudaGetSymbolAddress((void**)&A16, g_A16);
    cudaGetSymbolAddress((void**)&B1, g_B16_1);
    cudaGetSymbolAddress((void**)&B2, g_B16_2);
    cudaGetSymbolAddress((void**)&bufH8, g_bufH8);
    cudaGetSymbolAddress((void**)&bufH2, g_bufH2);
    cudaGetSymbolAddress((void**)&bnA, g_bnA);
    cudaGetSymbolAddress((void**)&bnB, g_bnB);
    cudaGetSymbolAddress((void**)&gmax, g_gmax);
    cudaGetSymbolAddress((void**)&sc1s, g_asrcv);
    cudaGetSymbolAddress((void**)&sc1d, g_adstv);
    cudaGetSymbolAddress((void**)&sc2s, g_asrcv2);
    cudaGetSymbolAddress((void**)&sc2d, g_adstv2);

    static cudaStream_t s2 = nullptr;
    static cudaEvent_t evF = nullptr, evJ = nullptr;
    if (s2 == nullptr) {
        cudaStreamCreateWithFlags(&s2, cudaStreamNonBlocking);
        cudaEventCreateWithFlags(&evF, cudaEventDisableTiming);
        cudaEventCreateWithFlags(&evJ, cudaEventDisableTiming);
    }

    const int GSMEM = 2 * GSTAGE;  // 54272
    cudaFuncSetAttribute(k_gemm_mma<0>, cudaFuncAttributeMaxDynamicSharedMemorySize, GSMEM);
    cudaFuncSetAttribute(k_gemm_mma<1>, cudaFuncAttributeMaxDynamicSharedMemorySize, GSMEM);

    int edgeBlocks = (TOTE + 255) / 256;

    // ---- fork ----
    cudaEventRecord(evF, 0);
    cudaStreamWaitEvent(s2, evF, 0);

    // branch A (main): fused prep + layer-1 GEMM
    k_prepAll<<<PREPA_BLKS + 129, 256>>>(x, W1, B1,
                                         b1, gam1, be1, m1, v1,
                                         b2, gam2, be2, m2, v2);
    // branch B (s2): layer-2 weight prep + edge count + CSR
    k_prepB2count<<<256 + (NEDGES + 255) / 256, 256, 0, s2>>>(W2, B2, ei);
    k_alloc<<<(NNODES + 255) / 256, 256, 0, s2>>>();
    k_fill<<<(NEDGES + 255) / 256, 256, 0, s2>>>(ei);
    k_sort<<<(NNODES + 255) / 256, 256, 0, s2>>>();
    cudaEventRecord(evJ, s2);

    k_gemm_mma<1><<<391, 512, GSMEM>>>(A16, B1, bufH8, 128, as1, ad1, sc1s, sc1d, gmax);

    // ---- join ----
    cudaStreamWaitEvent(0, evJ, 0);

    // layer 1: edge numerators + aggregation
    k_edgep<<<edgeBlocks, 256>>>(sc1s, sc1d, gmax);
    k_agg<0><<<(NNODES + 7) / 8, 256>>>(bufH8, bnA, bnB, nullptr);

    // layer 2
    k_gemm_mma<0><<<391, 512, GSMEM>>>(A16, B2, bufH2, 256, as2, ad2, sc2s, sc2d, gmax + 4);
    k_edgep<<<edgeBlocks, 256>>>(sc2s, sc2d, gmax + 4);
    k_agg<1><<<(NNODES + 7) / 8, 256>>>(bufH2, bnA + 256, bnB + 256, out);
}

// round 16
// speedup vs baseline: 1.0313x; 1.0313x over previous
#include <cuda_runtime.h>
#include <cuda_bf16.h>
#include <cuda_fp16.h>
#include <math.h>
#include <stdint.h>

#define NNODES 50000
#define NEDGES 800000
#define FDIM   256          // H*C
#define TOTE   (NEDGES + NNODES)

// ---------------- scratch (static device globals; no allocation) ----------------
__device__ __half   g_A16[(size_t)NNODES * FDIM];   // fp16 A operand
__device__ uint8_t  g_bufH8[(size_t)NNODES * FDIM]; // layer-1 h in fp8 e4m3 (agg0 gather src)
__device__ __half   g_bufH2[(size_t)NNODES * FDIM]; // layer-2 h in fp16 (agg1 gather src)
__device__ float g_asrcv[NNODES * 4];               // layer-1 scores
__device__ float g_adstv[NNODES * 4];
__device__ float g_asrcv2[NNODES * 4];              // layer-2 scores
__device__ float g_adstv2[NNODES * 4];
__device__ int   g_deg[NNODES];                     // invariant: zero at call entry
__device__ int2  g_rowseg[NNODES];                  // (start, end) of node's segment
__device__ int   g_cursor[NNODES];
__device__ int   g_srclist[TOTE];
__device__ int   g_allocCtr;
__device__ __half g_B16_1[32768];       // layer-1 weights fp16 [128][256]
__device__ __half g_B16_2[65536];       // layer-2 weights fp16 [256][256]
__device__ float g_bnA[512];
__device__ float g_bnB[512];
__device__ float g_gmax[8];             // per-head global max of asrc (layer slots)

// ---------------- PTX helpers ----------------
__device__ __forceinline__ uint32_t s2u(const void* p) {
    uint32_t a;
    asm("{ .reg .u64 t; cvta.to.shared.u64 t, %1; cvt.u32.u64 %0, t; }" : "=r"(a) : "l"(p));
    return a;
}

__device__ __forceinline__ void ldsm4(uint32_t* r, uint32_t addr) {
    asm volatile("ldmatrix.sync.aligned.m8n8.x4.shared.b16 {%0,%1,%2,%3}, [%4];"
                 : "=r"(r[0]), "=r"(r[1]), "=r"(r[2]), "=r"(r[3]) : "r"(addr));
}

__device__ __forceinline__ void ldsm4t(uint32_t* r, uint32_t addr) {
    asm volatile("ldmatrix.sync.aligned.m8n8.x4.trans.shared.b16 {%0,%1,%2,%3}, [%4];"
                 : "=r"(r[0]), "=r"(r[1]), "=r"(r[2]), "=r"(r[3]) : "r"(addr));
}

__device__ __forceinline__ void mma16816h(float* d, const uint32_t* a, const uint32_t* b) {
    asm volatile("mma.sync.aligned.m16n8k16.row.col.f32.f16.f16.f32 "
                 "{%0,%1,%2,%3}, {%4,%5,%6,%7}, {%8,%9}, {%0,%1,%2,%3};"
                 : "+f"(d[0]), "+f"(d[1]), "+f"(d[2]), "+f"(d[3])
                 : "r"(a[0]), "r"(a[1]), "r"(a[2]), "r"(a[3]), "r"(b[0]), "r"(b[1]));
}

__device__ __forceinline__ void cpasync16(uint32_t dst, const void* src, int sz) {
    asm volatile("cp.async.cg.shared.global [%0], [%1], 16, %2;"
                 :: "r"(dst), "l"(src), "r"(sz) : "memory");
}

__device__ __forceinline__ float lrelu(float e) {
    return (e > 0.f) ? e : 0.2f * e;
}

__device__ __forceinline__ void atomicMaxF(float* a, float v) {
    if (v >= 0.f) atomicMax((int*)a, __float_as_int(v));
    else atomicMin((unsigned int*)a, __float_as_uint(v));
}

__device__ __forceinline__ uint16_t pack_e4m3x2(float lo, float hi) {
    uint16_t p;
    asm("cvt.rn.satfinite.e4m3x2.f32 %0, %1, %2;" : "=h"(p) : "f"(hi), "f"(lo));
    return p;
}

__device__ __forceinline__ float2 fp8x2f(uint32_t v) {
    uint32_t h2;
    asm("cvt.rn.f16x2.e4m3x2 %0, %1;" : "=r"(h2) : "h"((uint16_t)v));
    return __half22float2(*(__half2*)&h2);
}

// ---------------- CSR build ----------------
__global__ void k_prepB2count(const float* __restrict__ W2, __half* __restrict__ B2,
                              const int* __restrict__ ei) {
    int b = blockIdx.x, t = threadIdx.x;
    if (b < 256) {
        int i = b * 256 + t;
        B2[i] = __float2half_rn(W2[i]);
    } else {
        int i = (b - 256) * 256 + t;
        if (i == 0) g_allocCtr = 0;
        if (i < NEDGES) atomicAdd(&g_deg[ei[NEDGES + i]], 1);
    }
}

// one-kernel segment allocation: block scans degrees, grabs range via one atomic.
// Placement varies across calls but per-node (sorted) content is identical -> deterministic.
__global__ void k_alloc() {
    __shared__ int s[256];
    __shared__ int base;
    int t = threadIdx.x;
    int i = blockIdx.x * 256 + t;
    int len = 0;
    if (i < NNODES) {
        len = g_deg[i] + 1;   // +1 self loop
        g_deg[i] = 0;         // restore zero invariant
    }
    s[t] = len;
    __syncthreads();
    for (int off = 1; off < 256; off <<= 1) {
        int u = (t >= off) ? s[t - off] : 0;
        __syncthreads();
        s[t] += u;
        __syncthreads();
    }
    if (t == 255) base = atomicAdd(&g_allocCtr, s[255]);
    __syncthreads();
    if (i < NNODES) {
        int r = base + s[t] - len;
        g_rowseg[i] = make_int2(r, r + len);
        g_srclist[r] = i;      // self loop first
        g_cursor[i] = r + 1;
    }
}

__global__ void k_fill(const int* __restrict__ ei) {
    int i = blockIdx.x * blockDim.x + threadIdx.x;
    if (i < NEDGES) {
        int s = ei[i];
        int d = ei[NEDGES + i];
        int pos = atomicAdd(&g_cursor[d], 1);
        g_srclist[pos] = s;
    }
}

// sort each node's segment by src (canonical order => deterministic sums)
__global__ void k_sort() {
    int n = blockIdx.x * blockDim.x + threadIdx.x;
    if (n >= NNODES) return;
    int2 rs = g_rowseg[n];
    int beg = rs.x + 1;
    int end = rs.y;
    int len = end - beg;
    if (len <= 1) return;
    if (len <= 56) {
        int buf[56];
        for (int i = 0; i < len; i++) buf[i] = g_srclist[beg + i];
        for (int i = 1; i < len; i++) {
            int key = buf[i];
            int j = i - 1;
            while (j >= 0 && buf[j] > key) {
                buf[j + 1] = buf[j];
                j--;
            }
            buf[j + 1] = key;
        }
        for (int i = 0; i < len; i++) g_srclist[beg + i] = buf[i];
    } else {
        for (int i = beg + 1; i < end; i++) {
            int key = g_srclist[i];
            int j = i - 1;
            while (j >= beg && g_srclist[j] > key) {
                g_srclist[j + 1] = g_srclist[j];
                j--;
            }
            g_srclist[j + 1] = key;
        }
    }
}

// ---------------- fused prep ----------------
#define PREPA_BLKS 25000     // 50000*128/256
__global__ void k_prepAll(const float* __restrict__ X,
                          const float* __restrict__ W1, __half* __restrict__ B1,
                          const float* __restrict__ b1, const float* __restrict__ g1,
                          const float* __restrict__ be1, const float* __restrict__ m1,
                          const float* __restrict__ v1,
                          const float* __restrict__ b2, const float* __restrict__ g2,
                          const float* __restrict__ be2, const float* __restrict__ m2,
                          const float* __restrict__ v2) {
    int b = blockIdx.x, t = threadIdx.x;
    if (b < PREPA_BLKS) {
        int i = b * 256 + t;
        g_A16[i] = __float2half_rn(X[i]);
    } else if (b < PREPA_BLKS + 128) {
        int i = (b - PREPA_BLKS) * 256 + t;
        B1[i] = __float2half_rn(W1[i]);
    } else {
        for (int i = t; i < 512; i += 256) {
            if (i < 256) {
                float s = g1[i] * rsqrtf(v1[i] + 1e-5f);
                g_bnA[i] = s;
                g_bnB[i] = (b1[i] - m1[i]) * s + be1[i];
            } else {
                int j = i - 256;
                float s = g2[j] * rsqrtf(v2[j] + 1e-5f);
                g_bnA[i] = s;
                g_bnB[i] = (b2[j] - m2[j]) * s + be2[j];
            }
        }
        if (t < 8) g_gmax[t] = -1e30f;
    }
}

// ---------------- fp16 tensor-core GEMM ----------------
#define GSTAGE 27136
template <int FP8OUT>
__global__ void __launch_bounds__(512) k_gemm_mma(const __half* __restrict__ Ap,
                                                  const __half* __restrict__ Bp,
                                                  void* __restrict__ Hout, int K,
                                                  const float* __restrict__ Asrc,
                                                  const float* __restrict__ Adst,
                                                  float* __restrict__ osrc,
                                                  float* __restrict__ odst,
                                                  float* __restrict__ gmax) {
    extern __shared__ char sm[];
    uint32_t sbase = s2u(sm);

    int tid = threadIdx.x;
    int lane = tid & 31, w = tid >> 5;
    int wm = w & 3, wn = w >> 2;
    int by = blockIdx.x;
    int nch = K >> 5;

    int ar = tid >> 2, ac = tid & 3;
    int agr = by * 128 + ar;
    int asz = (agr < NNODES) ? 16 : 0;
    int agc = (agr < NNODES) ? agr : 0;
    const char* gA = (const char*)(Ap + (size_t)agc * K + ac * 8);
    uint32_t dA = (uint32_t)(ar * 80 + ac * 16);

    float acc[2][8][4];
#pragma unroll
    for (int i = 0; i < 2; i++)
#pragma unroll
        for (int j = 0; j < 8; j++)
#pragma unroll
            for (int q = 0; q < 4; q++) acc[i][j][q] = 0.f;

#define ISSUE(kc, s) do {                                                          \
        uint32_t so = sbase + (s) * GSTAGE;                                        \
        cpasync16(so + dA, gA + (size_t)(kc) * 64, asz);                           \
        _Pragma("unroll")                                                          \
        for (int i = 0; i < 2; i++) {                                              \
            int p = tid + 512 * i;                                                 \
            int rr = p >> 5, c2 = p & 31;                                          \
            size_t go = (size_t)((kc) * 32 + rr) * 256 + c2 * 8;                   \
            cpasync16(so + 10240 + rr * 528 + c2 * 16, (const char*)(Bp + go), 16);\
        }                                                                          \
        asm volatile("cp.async.commit_group;" ::: "memory");                       \
    } while (0)

    ISSUE(0, 0);

    for (int kc = 0; kc < nch; kc++) {
        int s = kc & 1;
        if (kc + 1 < nch) {
            ISSUE(kc + 1, (kc + 1) & 1);
            asm volatile("cp.async.wait_group 1;" ::: "memory");
        } else {
            asm volatile("cp.async.wait_group 0;" ::: "memory");
        }
        __syncthreads();

        uint32_t aoff = sbase + s * GSTAGE;
        uint32_t boff = aoff + 10240;
#pragma unroll
        for (int ks = 0; ks < 2; ks++) {
            uint32_t av[2][4], bv[4][4];
#pragma unroll
            for (int mt = 0; mt < 2; mt++) {
                int row = wm * 32 + mt * 16 + (lane & 15);
                ldsm4(av[mt], aoff + row * 80 + ks * 32 + (lane >> 4) * 16);
            }
#pragma unroll
            for (int nt = 0; nt < 4; nt++) {
                int row = ks * 16 + (lane & 15);
                ldsm4t(bv[nt], boff + row * 528 + (wn * 64 + nt * 16) * 2 + (lane >> 4) * 16);
            }
#pragma unroll
            for (int mt = 0; mt < 2; mt++)
#pragma unroll
                for (int nt = 0; nt < 4; nt++)
#pragma unroll
                    for (int h = 0; h < 2; h++)
                        mma16816h(acc[mt][nt * 2 + h], av[mt], &bv[nt][h * 2]);
        }
        __syncthreads();
    }

    // ---- epilogue: write H (fp8 or fp16) + fused attention dots + global asrc max ----
    int head = wn;
    float wmax = -1e30f;
#pragma unroll
    for (int mt = 0; mt < 2; mt++) {
        int r0 = by * 128 + wm * 32 + mt * 16 + (lane >> 2);
        float ps0 = 0.f, ps1 = 0.f, pd0 = 0.f, pd1 = 0.f;
#pragma unroll
        for (int nt = 0; nt < 8; nt++) {
            int cc = wn * 64 + nt * 8 + (lane & 3) * 2;
            float as0 = Asrc[cc], as1v = Asrc[cc + 1];
            float ad0 = Adst[cc], ad1v = Adst[cc + 1];
            ps0 += acc[mt][nt][0] * as0 + acc[mt][nt][1] * as1v;
            pd0 += acc[mt][nt][0] * ad0 + acc[mt][nt][1] * ad1v;
            ps1 += acc[mt][nt][2] * as0 + acc[mt][nt][3] * as1v;
            pd1 += acc[mt][nt][2] * ad0 + acc[mt][nt][3] * ad1v;
            if (FP8OUT) {
                uint8_t* H8 = (uint8_t*)Hout;
                if (r0 < NNODES)
                    *(uint16_t*)(H8 + (size_t)r0 * FDIM + cc) =
                        pack_e4m3x2(acc[mt][nt][0], acc[mt][nt][1]);
                if (r0 + 8 < NNODES)
                    *(uint16_t*)(H8 + (size_t)(r0 + 8) * FDIM + cc) =
                        pack_e4m3x2(acc[mt][nt][2], acc[mt][nt][3]);
            } else {
                __half* H = (__half*)Hout;
                if (r0 < NNODES)
                    *(__half2*)(H + (size_t)r0 * FDIM + cc) =
                        __floats2half2_rn(acc[mt][nt][0], acc[mt][nt][1]);
                if (r0 + 8 < NNODES)
                    *(__half2*)(H + (size_t)(r0 + 8) * FDIM + cc) =
                        __floats2half2_rn(acc[mt][nt][2], acc[mt][nt][3]);
            }
        }
#pragma unroll
        for (int off = 1; off <= 2; off <<= 1) {
            ps0 += __shfl_xor_sync(0xffffffffu, ps0, off);
            ps1 += __shfl_xor_sync(0xffffffffu, ps1, off);
            pd0 += __shfl_xor_sync(0xffffffffu, pd0, off);
            pd1 += __shfl_xor_sync(0xffffffffu, pd1, off);
        }
        wmax = fmaxf(wmax, fmaxf(ps0, ps1));
        if ((lane & 3) == 0) {
            if (r0 < NNODES) {
                osrc[r0 * 4 + head] = ps0;
                odst[r0 * 4 + head] = pd0;
            }
            if (r0 + 8 < NNODES) {
                osrc[(r0 + 8) * 4 + head] = ps1;
                odst[(r0 + 8) * 4 + head] = pd1;
            }
        }
    }
#pragma unroll
    for (int off = 4; off <= 16; off <<= 1)
        wmax = fmaxf(wmax, __shfl_xor_sync(0xffffffffu, wmax, off));
    if (lane == 0) atomicMaxF(&gmax[head], wmax);
}

// ---------------- GAT aggregation: single-pass softmax vs global bound ----------------
// MODE 0: fp8 gather, write fp16 A operand. MODE 1: fp16 gather, log_softmax + fp32 out.
template <int MODE>
__global__ void __launch_bounds__(256) k_agg(const void* __restrict__ Xv,
                      const float* __restrict__ scs,
                      const float* __restrict__ scd,
                      const float* __restrict__ bnA,
                      const float* __restrict__ bnB,
                      const float* __restrict__ gmax,
                      float* __restrict__ OUT) {
    int gwarp = (blockIdx.x * blockDim.x + threadIdx.x) >> 5;
    int lane = threadIdx.x & 31;
    if (gwarp >= NNODES) return;
    int n = gwarp;
    int ch0 = lane * 8;
    int hl = lane >> 3;

    const int* __restrict__ lst = g_srclist;

    float adv = scd[n * 4 + hl];
    float mx = lrelu(gmax[hl] + adv);
    int2 rs = g_rowseg[n];
    int r0 = rs.x, r1 = rs.y;

    float dsum = 0.f;
    float acc[8];
#pragma unroll
    for (int j = 0; j < 8; j++) acc[j] = 0.f;

    int k = r0;
    if (MODE == 0) {
        const uint8_t* X8 = (const uint8_t*)Xv;
        for (; k + 3 < r1; k += 4) {
            int s0 = lst[k], s1 = lst[k + 1], s2 = lst[k + 2], s3 = lst[k + 3];
            uint2 ra = *(const uint2*)(X8 + (size_t)s0 * FDIM + ch0);
            uint2 rb = *(const uint2*)(X8 + (size_t)s1 * FDIM + ch0);
            uint2 rc = *(const uint2*)(X8 + (size_t)s2 * FDIM + ch0);
            uint2 rd = *(const uint2*)(X8 + (size_t)s3 * FDIM + ch0);
            float p0 = __expf(lrelu(scs[s0 * 4 + hl] + adv) - mx);
            float p1 = __expf(lrelu(scs[s1 * 4 + hl] + adv) - mx);
            float p2 = __expf(lrelu(scs[s2 * 4 + hl] + adv) - mx);
            float p3 = __expf(lrelu(scs[s3 * 4 + hl] + adv) - mx);
            dsum += (p0 + p1) + (p2 + p3);
            float2 a0 = fp8x2f(ra.x), a1 = fp8x2f(ra.x >> 16), a2 = fp8x2f(ra.y), a3 = fp8x2f(ra.y >> 16);
            float2 b0 = fp8x2f(rb.x), b1 = fp8x2f(rb.x >> 16), b2 = fp8x2f(rb.y), b3 = fp8x2f(rb.y >> 16);
            float2 c0 = fp8x2f(rc.x), c1 = fp8x2f(rc.x >> 16), c2 = fp8x2f(rc.y), c3 = fp8x2f(rc.y >> 16);
            float2 d0 = fp8x2f(rd.x), d1 = fp8x2f(rd.x >> 16), d2 = fp8x2f(rd.y), d3 = fp8x2f(rd.y >> 16);
            acc[0] += (p0 * a0.x + p1 * b0.x) + (p2 * c0.x + p3 * d0.x);
            acc[1] += (p0 * a0.y + p1 * b0.y) + (p2 * c0.y + p3 * d0.y);
            acc[2] += (p0 * a1.x + p1 * b1.x) + (p2 * c1.x + p3 * d1.x);
            acc[3] += (p0 * a1.y + p1 * b1.y) + (p2 * c1.y + p3 * d1.y);
            acc[4] += (p0 * a2.x + p1 * b2.x) + (p2 * c2.x + p3 * d2.x);
            acc[5] += (p0 * a2.y + p1 * b2.y) + (p2 * c2.y + p3 * d2.y);
            acc[6] += (p0 * a3.x + p1 * b3.x) + (p2 * c3.x + p3 * d3.x);
            acc[7] += (p0 * a3.y + p1 * b3.y) + (p2 * c3.y + p3 * d3.y);
        }
        for (; k < r1; k++) {
            int s0 = lst[k];
            uint2 ra = *(const uint2*)(X8 + (size_t)s0 * FDIM + ch0);
            float p0 = __expf(lrelu(scs[s0 * 4 + hl] + adv) - mx);
            dsum += p0;
            float2 a0 = fp8x2f(ra.x), a1 = fp8x2f(ra.x >> 16), a2 = fp8x2f(ra.y), a3 = fp8x2f(ra.y >> 16);
            acc[0] += p0 * a0.x;
            acc[1] += p0 * a0.y;
            acc[2] += p0 * a1.x;
            acc[3] += p0 * a1.y;
            acc[4] += p0 * a2.x;
            acc[5] += p0 * a2.y;
            acc[6] += p0 * a3.x;
            acc[7] += p0 * a3.y;
        }
    } else {
        const __half* X = (const __half*)Xv;
        for (; k + 3 < r1; k += 4) {
            int s0 = lst[k], s1 = lst[k + 1], s2 = lst[k + 2], s3 = lst[k + 3];
            uint4 ra = *(const uint4*)(X + (size_t)s0 * FDIM + ch0);
            uint4 rb = *(const uint4*)(X + (size_t)s1 * FDIM + ch0);
            uint4 rc = *(const uint4*)(X + (size_t)s2 * FDIM + ch0);
            uint4 rd = *(const uint4*)(X + (size_t)s3 * FDIM + ch0);
            float p0 = __expf(lrelu(scs[s0 * 4 + hl] + adv) - mx);
            float p1 = __expf(lrelu(scs[s1 * 4 + hl] + adv) - mx);
            float p2 = __expf(lrelu(scs[s2 * 4 + hl] + adv) - mx);
            float p3 = __expf(lrelu(scs[s3 * 4 + hl] + adv) - mx);
            dsum += (p0 + p1) + (p2 + p3);
            float2 a0 = __half22float2(*(__half2*)&ra.x);
            float2 a1 = __half22float2(*(__half2*)&ra.y);
            float2 a2 = __half22float2(*(__half2*)&ra.z);
            float2 a3 = __half22float2(*(__half2*)&ra.w);
            float2 b0 = __half22float2(*(__half2*)&rb.x);
            float2 b1 = __half22float2(*(__half2*)&rb.y);
            float2 b2 = __half22float2(*(__half2*)&rb.z);
            float2 b3 = __half22float2(*(__half2*)&rb.w);
            float2 c0 = __half22float2(*(__half2*)&rc.x);
            float2 c1 = __half22float2(*(__half2*)&rc.y);
            float2 c2 = __half22float2(*(__half2*)&rc.z);
            float2 c3 = __half22float2(*(__half2*)&rc.w);
            float2 d0 = __half22float2(*(__half2*)&rd.x);
            float2 d1 = __half22float2(*(__half2*)&rd.y);
            float2 d2 = __half22float2(*(__half2*)&rd.z);
            float2 d3 = __half22float2(*(__half2*)&rd.w);
            acc[0] += (p0 * a0.x + p1 * b0.x) + (p2 * c0.x + p3 * d0.x);
            acc[1] += (p0 * a0.y + p1 * b0.y) + (p2 * c0.y + p3 * d0.y);
            acc[2] += (p0 * a1.x + p1 * b1.x) + (p2 * c1.x + p3 * d1.x);
            acc[3] += (p0 * a1.y + p1 * b1.y) + (p2 * c1.y + p3 * d1.y);
            acc[4] += (p0 * a2.x + p1 * b2.x) + (p2 * c2.x + p3 * d2.x);
            acc[5] += (p0 * a2.y + p1 * b2.y) + (p2 * c2.y + p3 * d2.y);
            acc[6] += (p0 * a3.x + p1 * b3.x) + (p2 * c3.x + p3 * d3.x);
            acc[7] += (p0 * a3.y + p1 * b3.y) + (p2 * c3.y + p3 * d3.y);
        }
        for (; k < r1; k++) {
            int s0 = lst[k];
            uint4 ra = *(const uint4*)(X + (size_t)s0 * FDIM + ch0);
            float p0 = __expf(lrelu(scs[s0 * 4 + hl] + adv) - mx);
            dsum += p0;
            float2 a0 = __half22float2(*(__half2*)&ra.x);
            float2 a1 = __half22float2(*(__half2*)&ra.y);
            float2 a2 = __half22float2(*(__half2*)&ra.z);
            float2 a3 = __half22float2(*(__half2*)&ra.w);
            acc[0] += p0 * a0.x;
            acc[1] += p0 * a0.y;
            acc[2] += p0 * a1.x;
            acc[3] += p0 * a1.y;
            acc[4] += p0 * a2.x;
            acc[5] += p0 * a2.y;
            acc[6] += p0 * a3.x;
            acc[7] += p0 * a3.y;
        }
    }

    float inv = 1.f / (dsum + 1e-16f);
    float ov[8];
#pragma unroll
    for (int j = 0; j < 8; j++) {
        int ch = ch0 + j;
        ov[j] = fmaxf(fmaf(acc[j] * inv, bnA[ch], bnB[ch]), 0.f);
    }

    if (MODE == 0) {
        uint4 hv;
        *(__half2*)&hv.x = __floats2half2_rn(ov[0], ov[1]);
        *(__half2*)&hv.y = __floats2half2_rn(ov[2], ov[3]);
        *(__half2*)&hv.z = __floats2half2_rn(ov[4], ov[5]);
        *(__half2*)&hv.w = __floats2half2_rn(ov[6], ov[7]);
        *(uint4*)(g_A16 + (size_t)n * FDIM + ch0) = hv;
    } else {
        float m2 = ov[0];
#pragma unroll
        for (int j = 1; j < 8; j++) m2 = fmaxf(m2, ov[j]);
#pragma unroll
        for (int off = 16; off > 0; off >>= 1) m2 = fmaxf(m2, __shfl_xor_sync(0xffffffffu, m2, off));
        float se = 0.f;
#pragma unroll
        for (int j = 0; j < 8; j++) se += __expf(ov[j] - m2);
#pragma unroll
        for (int off = 16; off > 0; off >>= 1) se += __shfl_xor_sync(0xffffffffu, se, off);
        float lse = m2 + logf(se);
        float4* op = (float4*)(OUT + (size_t)n * FDIM + ch0);
        op[0] = make_float4(ov[0] - lse, ov[1] - lse, ov[2] - lse, ov[3] - lse);
        op[1] = make_float4(ov[4] - lse, ov[5] - lse, ov[6] - lse, ov[7] - lse);
    }
}

// ---------------- launch ----------------
extern "C" void kernel_launch(void* const* d_in, const int* in_sizes, int n_in,
                              void* d_out, int out_size) {
    const float* x    = (const float*)d_in[0];
    const int*   ei   = (const int*)d_in[1];
    const float* W1   = (const float*)d_in[2];
    const float* as1  = (const float*)d_in[3];
    const float* ad1  = (const float*)d_in[4];
    const float* b1   = (const float*)d_in[5];
    const float* gam1 = (const float*)d_in[6];
    const float* be1  = (const float*)d_in[7];
    const float* m1   = (const float*)d_in[8];
    const float* v1   = (const float*)d_in[9];
    const float* W2   = (const float*)d_in[10];
    const float* as2  = (const float*)d_in[11];
    const float* ad2  = (const float*)d_in[12];
    const float* b2   = (const float*)d_in[13];
    const float* gam2 = (const float*)d_in[14];
    const float* be2  = (const float*)d_in[15];
    const float* m2   = (const float*)d_in[16];
    const float* v2   = (const float*)d_in[17];
    float* out = (float*)d_out;

    __half *A16, *B1, *B2, *bufH2;
    uint8_t *bufH8;
    float *bnA, *bnB, *gmax, *sc1s, *sc1d, *sc2s, *sc2d;
    cudaGetSymbolAddress((void**)&A16, g_A16);
    cudaGetSymbolAddress((void**)&B1, g_B16_1);
    cudaGetSymbolAddress((void**)&B2, g_B16_2);
    cudaGetSymbolAddress((void**)&bufH8, g_bufH8);
    cudaGetSymbolAddress((void**)&bufH2, g_bufH2);
    cudaGetSymbolAddress((void**)&bnA, g_bnA);
    cudaGetSymbolAddress((void**)&bnB, g_bnB);
    cudaGetSymbolAddress((void**)&gmax, g_gmax);
    cudaGetSymbolAddress((void**)&sc1s, g_asrcv);
    cudaGetSymbolAddress((void**)&sc1d, g_adstv);
    cudaGetSymbolAddress((void**)&sc2s, g_asrcv2);
    cudaGetSymbolAddress((void**)&sc2d, g_adstv2);

    static cudaStream_t s2 = nullptr;
    static cudaEvent_t evF = nullptr, evJ = nullptr;
    if (s2 == nullptr) {
        cudaStreamCreateWithFlags(&s2, cudaStreamNonBlocking);
        cudaEventCreateWithFlags(&evF, cudaEventDisableTiming);
        cudaEventCreateWithFlags(&evJ, cudaEventDisableTiming);
    }

    const int GSMEM = 2 * GSTAGE;  // 54272
    cudaFuncSetAttribute(k_gemm_mma<0>, cudaFuncAttributeMaxDynamicSharedMemorySize, GSMEM);
    cudaFuncSetAttribute(k_gemm_mma<1>, cudaFuncAttributeMaxDynamicSharedMemorySize, GSMEM);

    // ---- fork ----
    cudaEventRecord(evF, 0);
    cudaStreamWaitEvent(s2, evF, 0);

    // branch A (main): fused prep + layer-1 GEMM
    k_prepAll<<<PREPA_BLKS + 129, 256>>>(x, W1, B1,
                                         b1, gam1, be1, m1, v1,
                                         b2, gam2, be2, m2, v2);
    // branch B (s2): layer-2 weight prep + edge count + CSR
    k_prepB2count<<<256 + (NEDGES + 255) / 256, 256, 0, s2>>>(W2, B2, ei);
    k_alloc<<<(NNODES + 255) / 256, 256, 0, s2>>>();
    k_fill<<<(NEDGES + 255) / 256, 256, 0, s2>>>(ei);
    k_sort<<<(NNODES + 255) / 256, 256, 0, s2>>>();
    cudaEventRecord(evJ, s2);

    k_gemm_mma<1><<<391, 512, GSMEM>>>(A16, B1, bufH8, 128, as1, ad1, sc1s, sc1d, gmax);

    // ---- join ----
    cudaStreamWaitEvent(0, evJ, 0);

    // layer 1 aggregation (fp8 gather)
    k_agg<0><<<(NNODES + 7) / 8, 256>>>(bufH8, sc1s, sc1d, bnA, bnB, gmax, nullptr);

    // layer 2
    k_gemm_mma<0><<<391, 512, GSMEM>>>(A16, B2, bufH2, 256, as2, ad2, sc2s, sc2d, gmax + 4);
    k_agg<1><<<(NNODES + 7) / 8, 256>>>(bufH2, sc2s, sc2d, bnA + 256, bnB + 256, gmax + 4, out);
}

// round 17
// speedup vs baseline: 1.0439x; 1.0122x over previous
#include <cuda_runtime.h>
#include <cuda_bf16.h>
#include <cuda_fp16.h>
#include <math.h>
#include <stdint.h>

#define NNODES 50000
#define NEDGES 800000
#define FDIM   256          // H*C
#define TOTE   (NEDGES + NNODES)

// ---------------- scratch (static device globals; no allocation) ----------------
__device__ __half   g_A16[(size_t)NNODES * FDIM];   // fp16 A operand
__device__ uint8_t  g_bufH8[(size_t)NNODES * FDIM]; // layer-1 h in fp8 e4m3 (agg0 gather src)
__device__ __half   g_bufH2[(size_t)NNODES * FDIM]; // layer-2 h in fp16 (agg1 gather src)
__device__ float g_asrcv[NNODES * 4];               // layer-1 scores
__device__ float g_adstv[NNODES * 4];
__device__ float g_asrcv2[NNODES * 4];              // layer-2 scores
__device__ float g_adstv2[NNODES * 4];
__device__ int   g_deg[NNODES];                     // invariant: zero at call entry
__device__ int2  g_rowseg[NNODES];                  // (start, end) of node's segment
__device__ int   g_cursor[NNODES];
__device__ int   g_srclist[TOTE];
__device__ int   g_allocCtr;
__device__ __half g_B16_1[32768];       // layer-1 weights fp16 [128][256]
__device__ __half g_B16_2[65536];       // layer-2 weights fp16 [256][256]
__device__ float g_bnA[512];
__device__ float g_bnB[512];
__device__ float g_gmax[8];             // per-head global max of asrc (layer slots)

// ---------------- PTX helpers ----------------
__device__ __forceinline__ uint32_t s2u(const void* p) {
    uint32_t a;
    asm("{ .reg .u64 t; cvta.to.shared.u64 t, %1; cvt.u32.u64 %0, t; }" : "=r"(a) : "l"(p));
    return a;
}

__device__ __forceinline__ void ldsm4(uint32_t* r, uint32_t addr) {
    asm volatile("ldmatrix.sync.aligned.m8n8.x4.shared.b16 {%0,%1,%2,%3}, [%4];"
                 : "=r"(r[0]), "=r"(r[1]), "=r"(r[2]), "=r"(r[3]) : "r"(addr));
}

__device__ __forceinline__ void ldsm4t(uint32_t* r, uint32_t addr) {
    asm volatile("ldmatrix.sync.aligned.m8n8.x4.trans.shared.b16 {%0,%1,%2,%3}, [%4];"
                 : "=r"(r[0]), "=r"(r[1]), "=r"(r[2]), "=r"(r[3]) : "r"(addr));
}

__device__ __forceinline__ void mma16816h(float* d, const uint32_t* a, const uint32_t* b) {
    asm volatile("mma.sync.aligned.m16n8k16.row.col.f32.f16.f16.f32 "
                 "{%0,%1,%2,%3}, {%4,%5,%6,%7}, {%8,%9}, {%0,%1,%2,%3};"
                 : "+f"(d[0]), "+f"(d[1]), "+f"(d[2]), "+f"(d[3])
                 : "r"(a[0]), "r"(a[1]), "r"(a[2]), "r"(a[3]), "r"(b[0]), "r"(b[1]));
}

__device__ __forceinline__ void cpasync16(uint32_t dst, const void* src, int sz) {
    asm volatile("cp.async.cg.shared.global [%0], [%1], 16, %2;"
                 :: "r"(dst), "l"(src), "r"(sz) : "memory");
}

__device__ __forceinline__ float lrelu(float e) {
    return (e > 0.f) ? e : 0.2f * e;
}

__device__ __forceinline__ void atomicMaxF(float* a, float v) {
    if (v >= 0.f) atomicMax((int*)a, __float_as_int(v));
    else atomicMin((unsigned int*)a, __float_as_uint(v));
}

__device__ __forceinline__ uint16_t pack_e4m3x2(float lo, float hi) {
    uint16_t p;
    asm("cvt.rn.satfinite.e4m3x2.f32 %0, %1, %2;" : "=h"(p) : "f"(hi), "f"(lo));
    return p;
}

__device__ __forceinline__ float2 fp8x2f(uint32_t v) {
    uint32_t h2;
    asm("cvt.rn.f16x2.e4m3x2 %0, %1;" : "=r"(h2) : "h"((uint16_t)v));
    return __half22float2(*(__half2*)&h2);
}

// ---------------- CSR build ----------------
__global__ void k_count(const int* __restrict__ ei) {
    int i = blockIdx.x * blockDim.x + threadIdx.x;
    if (i == 0) g_allocCtr = 0;
    if (i < NEDGES) atomicAdd(&g_deg[ei[NEDGES + i]], 1);
}

// one-kernel segment allocation: block scans degrees, grabs range via one atomic.
// Placement varies across calls but per-node (sorted) content is identical -> deterministic.
__global__ void k_alloc() {
    __shared__ int s[256];
    __shared__ int base;
    int t = threadIdx.x;
    int i = blockIdx.x * 256 + t;
    int len = 0;
    if (i < NNODES) {
        len = g_deg[i] + 1;   // +1 self loop
        g_deg[i] = 0;         // restore zero invariant
    }
    s[t] = len;
    __syncthreads();
    for (int off = 1; off < 256; off <<= 1) {
        int u = (t >= off) ? s[t - off] : 0;
        __syncthreads();
        s[t] += u;
        __syncthreads();
    }
    if (t == 255) base = atomicAdd(&g_allocCtr, s[255]);
    __syncthreads();
    if (i < NNODES) {
        int r = base + s[t] - len;
        g_rowseg[i] = make_int2(r, r + len);
        g_srclist[r] = i;      // self loop first
        g_cursor[i] = r + 1;
    }
}

__global__ void k_fill(const int* __restrict__ ei) {
    int i = blockIdx.x * blockDim.x + threadIdx.x;
    if (i < NEDGES) {
        int s = ei[i];
        int d = ei[NEDGES + i];
        int pos = atomicAdd(&g_cursor[d], 1);
        g_srclist[pos] = s;
    }
}

// sort each node's segment by src (canonical order => deterministic sums)
__global__ void k_sort() {
    int n = blockIdx.x * blockDim.x + threadIdx.x;
    if (n >= NNODES) return;
    int2 rs = g_rowseg[n];
    int beg = rs.x + 1;
    int end = rs.y;
    int len = end - beg;
    if (len <= 1) return;
    if (len <= 56) {
        int buf[56];
        for (int i = 0; i < len; i++) buf[i] = g_srclist[beg + i];
        for (int i = 1; i < len; i++) {
            int key = buf[i];
            int j = i - 1;
            while (j >= 0 && buf[j] > key) {
                buf[j + 1] = buf[j];
                j--;
            }
            buf[j + 1] = key;
        }
        for (int i = 0; i < len; i++) g_srclist[beg + i] = buf[i];
    } else {
        for (int i = beg + 1; i < end; i++) {
            int key = g_srclist[i];
            int j = i - 1;
            while (j >= beg && g_srclist[j] > key) {
                g_srclist[j + 1] = g_srclist[j];
                j--;
            }
            g_srclist[j + 1] = key;
        }
    }
}

// ---------------- fused prep: A16 + W1 + W2 + BN + gmax ----------------
#define PREPA_BLKS 25000     // 50000*128/256
__global__ void k_prepAll(const float* __restrict__ X,
                          const float* __restrict__ W1, __half* __restrict__ B1,
                          const float* __restrict__ W2, __half* __restrict__ B2,
                          const float* __restrict__ b1, const float* __restrict__ g1,
                          const float* __restrict__ be1, const float* __restrict__ m1,
                          const float* __restrict__ v1,
                          const float* __restrict__ b2, const float* __restrict__ g2,
                          const float* __restrict__ be2, const float* __restrict__ m2,
                          const float* __restrict__ v2) {
    int b = blockIdx.x, t = threadIdx.x;
    if (b < PREPA_BLKS) {
        int i = b * 256 + t;
        g_A16[i] = __float2half_rn(X[i]);
    } else if (b < PREPA_BLKS + 128) {
        int i = (b - PREPA_BLKS) * 256 + t;
        B1[i] = __float2half_rn(W1[i]);
    } else if (b < PREPA_BLKS + 128 + 256) {
        int i = (b - PREPA_BLKS - 128) * 256 + t;
        B2[i] = __float2half_rn(W2[i]);
    } else {
        for (int i = t; i < 512; i += 256) {
            if (i < 256) {
                float s = g1[i] * rsqrtf(v1[i] + 1e-5f);
                g_bnA[i] = s;
                g_bnB[i] = (b1[i] - m1[i]) * s + be1[i];
            } else {
                int j = i - 256;
                float s = g2[j] * rsqrtf(v2[j] + 1e-5f);
                g_bnA[i] = s;
                g_bnB[i] = (b2[j] - m2[j]) * s + be2[j];
            }
        }
        if (t < 8) g_gmax[t] = -1e30f;
    }
}

// ---------------- fp16 tensor-core GEMM: 256 thr, 128x128 tile, 2 CTAs/SM ----------------
// stage: A[128][80B] (10240) + B[32][272B] (8704) = 18944 B; 2 stages = 37888.
#define GSTAGE 18944
template <int FP8OUT>
__global__ void __launch_bounds__(256, 2) k_gemm_mma(const __half* __restrict__ Ap,
                                                     const __half* __restrict__ Bp,
                                                     void* __restrict__ Hout, int K,
                                                     const float* __restrict__ Asrc,
                                                     const float* __restrict__ Adst,
                                                     float* __restrict__ osrc,
                                                     float* __restrict__ odst,
                                                     float* __restrict__ gmax) {
    extern __shared__ char sm[];
    uint32_t sbase = s2u(sm);

    int tid = threadIdx.x;
    int lane = tid & 31, w = tid >> 5;
    int wm = w & 3, wn = w >> 2;           // warp tile (wm*32, wn*64); wn in {0,1}
    int bx = blockIdx.x;                   // N half: 0 or 1
    int by = blockIdx.y;
    int nch = K >> 5;

    // A load: 2 threads/row, each thread 2x16B (row chunk = 64B)
    int ar = tid >> 1, ac = tid & 1;
    int agr = by * 128 + ar;
    int asz = (agr < NNODES) ? 16 : 0;
    int agc = (agr < NNODES) ? agr : 0;
    const char* gA = (const char*)(Ap + (size_t)agc * K) + ac * 16;
    uint32_t dA = (uint32_t)(ar * 80 + ac * 16);

    float acc[2][8][4];
#pragma unroll
    for (int i = 0; i < 2; i++)
#pragma unroll
        for (int j = 0; j < 8; j++)
#pragma unroll
            for (int q = 0; q < 4; q++) acc[i][j][q] = 0.f;

#define ISSUE(kc, s) do {                                                            \
        uint32_t so = sbase + (s) * GSTAGE;                                          \
        cpasync16(so + dA, gA + (size_t)(kc) * 64, asz);                             \
        cpasync16(so + dA + 32, gA + (size_t)(kc) * 64 + 32, asz);                   \
        _Pragma("unroll")                                                            \
        for (int i = 0; i < 2; i++) {                                                \
            int p = tid + 256 * i;                                                   \
            int rr = p >> 4, c2 = p & 15;                                            \
            size_t go = (size_t)((kc) * 32 + rr) * 256 + bx * 128 + c2 * 8;          \
            cpasync16(so + 10240 + rr * 272 + c2 * 16, (const char*)(Bp + go), 16);  \
        }                                                                            \
        asm volatile("cp.async.commit_group;" ::: "memory");                         \
    } while (0)

    ISSUE(0, 0);

    for (int kc = 0; kc < nch; kc++) {
        int s = kc & 1;
        if (kc + 1 < nch) {
            ISSUE(kc + 1, (kc + 1) & 1);
            asm volatile("cp.async.wait_group 1;" ::: "memory");
        } else {
            asm volatile("cp.async.wait_group 0;" ::: "memory");
        }
        __syncthreads();

        uint32_t aoff = sbase + s * GSTAGE;
        uint32_t boff = aoff + 10240;
#pragma unroll
        for (int ks = 0; ks < 2; ks++) {
            uint32_t av[2][4], bv[4][4];
#pragma unroll
            for (int mt = 0; mt < 2; mt++) {
                int row = wm * 32 + mt * 16 + (lane & 15);
                ldsm4(av[mt], aoff + row * 80 + ks * 32 + (lane >> 4) * 16);
            }
#pragma unroll
            for (int nt = 0; nt < 4; nt++) {
                int row = ks * 16 + (lane & 15);
                ldsm4t(bv[nt], boff + row * 272 + (wn * 64 + nt * 16) * 2 + (lane >> 4) * 16);
            }
#pragma unroll
            for (int mt = 0; mt < 2; mt++)
#pragma unroll
                for (int nt = 0; nt < 4; nt++)
#pragma unroll
                    for (int h = 0; h < 2; h++)
                        mma16816h(acc[mt][nt * 2 + h], av[mt], &bv[nt][h * 2]);
        }
        __syncthreads();
    }

    // ---- epilogue: write H (fp8 or fp16) + fused attention dots + global asrc max ----
    int head = bx * 2 + wn;
    float wmax = -1e30f;
#pragma unroll
    for (int mt = 0; mt < 2; mt++) {
        int r0 = by * 128 + wm * 32 + mt * 16 + (lane >> 2);
        float ps0 = 0.f, ps1 = 0.f, pd0 = 0.f, pd1 = 0.f;
#pragma unroll
        for (int nt = 0; nt < 8; nt++) {
            int cc = bx * 128 + wn * 64 + nt * 8 + (lane & 3) * 2;
            float as0 = Asrc[cc], as1v = Asrc[cc + 1];
            float ad0 = Adst[cc], ad1v = Adst[cc + 1];
            ps0 += acc[mt][nt][0] * as0 + acc[mt][nt][1] * as1v;
            pd0 += acc[mt][nt][0] * ad0 + acc[mt][nt][1] * ad1v;
            ps1 += acc[mt][nt][2] * as0 + acc[mt][nt][3] * as1v;
            pd1 += acc[mt][nt][2] * ad0 + acc[mt][nt][3] * ad1v;
            if (FP8OUT) {
                uint8_t* H8 = (uint8_t*)Hout;
                if (r0 < NNODES)
                    *(uint16_t*)(H8 + (size_t)r0 * FDIM + cc) =
                        pack_e4m3x2(acc[mt][nt][0], acc[mt][nt][1]);
                if (r0 + 8 < NNODES)
                    *(uint16_t*)(H8 + (size_t)(r0 + 8) * FDIM + cc) =
                        pack_e4m3x2(acc[mt][nt][2], acc[mt][nt][3]);
            } else {
                __half* H = (__half*)Hout;
                if (r0 < NNODES)
                    *(__half2*)(H + (size_t)r0 * FDIM + cc) =
                        __floats2half2_rn(acc[mt][nt][0], acc[mt][nt][1]);
                if (r0 + 8 < NNODES)
                    *(__half2*)(H + (size_t)(r0 + 8) * FDIM + cc) =
                        __floats2half2_rn(acc[mt][nt][2], acc[mt][nt][3]);
            }
        }
#pragma unroll
        for (int off = 1; off <= 2; off <<= 1) {
            ps0 += __shfl_xor_sync(0xffffffffu, ps0, off);
            ps1 += __shfl_xor_sync(0xffffffffu, ps1, off);
            pd0 += __shfl_xor_sync(0xffffffffu, pd0, off);
            pd1 += __shfl_xor_sync(0xffffffffu, pd1, off);
        }
        wmax = fmaxf(wmax, fmaxf(ps0, ps1));
        if ((lane & 3) == 0) {
            if (r0 < NNODES) {
                osrc[r0 * 4 + head] = ps0;
                odst[r0 * 4 + head] = pd0;
            }
            if (r0 + 8 < NNODES) {
                osrc[(r0 + 8) * 4 + head] = ps1;
                odst[(r0 + 8) * 4 + head] = pd1;
            }
        }
    }
#pragma unroll
    for (int off = 4; off <= 16; off <<= 1)
        wmax = fmaxf(wmax, __shfl_xor_sync(0xffffffffu, wmax, off));
    if (lane == 0) atomicMaxF(&gmax[head], wmax);
}

// ---------------- GAT aggregation: single-pass softmax vs global bound ----------------
// MODE 0: fp8 gather, write fp16 A operand. MODE 1: fp16 gather, log_softmax + fp32 out.
template <int MODE>
__global__ void __launch_bounds__(256) k_agg(const void* __restrict__ Xv,
                      const float* __restrict__ scs,
                      const float* __restrict__ scd,
                      const float* __restrict__ bnA,
                      const float* __restrict__ bnB,
                      const float* __restrict__ gmax,
                      float* __restrict__ OUT) {
    int gwarp = (blockIdx.x * blockDim.x + threadIdx.x) >> 5;
    int lane = threadIdx.x & 31;
    if (gwarp >= NNODES) return;
    int n = gwarp;
    int ch0 = lane * 8;
    int hl = lane >> 3;

    const int* __restrict__ lst = g_srclist;

    float adv = scd[n * 4 + hl];
    float mx = lrelu(gmax[hl] + adv);
    int2 rs = g_rowseg[n];
    int r0 = rs.x, r1 = rs.y;

    float dsum = 0.f;
    float acc[8];
#pragma unroll
    for (int j = 0; j < 8; j++) acc[j] = 0.f;

    int k = r0;
    if (MODE == 0) {
        const uint8_t* X8 = (const uint8_t*)Xv;
        for (; k + 3 < r1; k += 4) {
            int s0 = lst[k], s1 = lst[k + 1], s2 = lst[k + 2], s3 = lst[k + 3];
            uint2 ra = *(const uint2*)(X8 + (size_t)s0 * FDIM + ch0);
            uint2 rb = *(const uint2*)(X8 + (size_t)s1 * FDIM + ch0);
            uint2 rc = *(const uint2*)(X8 + (size_t)s2 * FDIM + ch0);
            uint2 rd = *(const uint2*)(X8 + (size_t)s3 * FDIM + ch0);
            float p0 = __expf(lrelu(scs[s0 * 4 + hl] + adv) - mx);
            float p1 = __expf(lrelu(scs[s1 * 4 + hl] + adv) - mx);
            float p2 = __expf(lrelu(scs[s2 * 4 + hl] + adv) - mx);
            float p3 = __expf(lrelu(scs[s3 * 4 + hl] + adv) - mx);
            dsum += (p0 + p1) + (p2 + p3);
            float2 a0 = fp8x2f(ra.x), a1 = fp8x2f(ra.x >> 16), a2 = fp8x2f(ra.y), a3 = fp8x2f(ra.y >> 16);
            float2 b0 = fp8x2f(rb.x), b1 = fp8x2f(rb.x >> 16), b2 = fp8x2f(rb.y), b3 = fp8x2f(rb.y >> 16);
            float2 c0 = fp8x2f(rc.x), c1 = fp8x2f(rc.x >> 16), c2 = fp8x2f(rc.y), c3 = fp8x2f(rc.y >> 16);
            float2 d0 = fp8x2f(rd.x), d1 = fp8x2f(rd.x >> 16), d2 = fp8x2f(rd.y), d3 = fp8x2f(rd.y >> 16);
            acc[0] += (p0 * a0.x + p1 * b0.x) + (p2 * c0.x + p3 * d0.x);
            acc[1] += (p0 * a0.y + p1 * b0.y) + (p2 * c0.y + p3 * d0.y);
            acc[2] += (p0 * a1.x + p1 * b1.x) + (p2 * c1.x + p3 * d1.x);
            acc[3] += (p0 * a1.y + p1 * b1.y) + (p2 * c1.y + p3 * d1.y);
            acc[4] += (p0 * a2.x + p1 * b2.x) + (p2 * c2.x + p3 * d2.x);
            acc[5] += (p0 * a2.y + p1 * b2.y) + (p2 * c2.y + p3 * d2.y);
            acc[6] += (p0 * a3.x + p1 * b3.x) + (p2 * c3.x + p3 * d3.x);
            acc[7] += (p0 * a3.y + p1 * b3.y) + (p2 * c3.y + p3 * d3.y);
        }
        for (; k < r1; k++) {
            int s0 = lst[k];
            uint2 ra = *(const uint2*)(X8 + (size_t)s0 * FDIM + ch0);
            float p0 = __expf(lrelu(scs[s0 * 4 + hl] + adv) - mx);
            dsum += p0;
            float2 a0 = fp8x2f(ra.x), a1 = fp8x2f(ra.x >> 16), a2 = fp8x2f(ra.y), a3 = fp8x2f(ra.y >> 16);
            acc[0] += p0 * a0.x;
            acc[1] += p0 * a0.y;
            acc[2] += p0 * a1.x;
            acc[3] += p0 * a1.y;
            acc[4] += p0 * a2.x;
            acc[5] += p0 * a2.y;
            acc[6] += p0 * a3.x;
            acc[7] += p0 * a3.y;
        }
    } else {
        const __half* X = (const __half*)Xv;
        for (; k + 3 < r1; k += 4) {
            int s0 = lst[k], s1 = lst[k + 1], s2 = lst[k + 2], s3 = lst[k + 3];
            uint4 ra = *(const uint4*)(X + (size_t)s0 * FDIM + ch0);
            uint4 rb = *(const uint4*)(X + (size_t)s1 * FDIM + ch0);
            uint4 rc = *(const uint4*)(X + (size_t)s2 * FDIM + ch0);
            uint4 rd = *(const uint4*)(X + (size_t)s3 * FDIM + ch0);
            float p0 = __expf(lrelu(scs[s0 * 4 + hl] + adv) - mx);
            float p1 = __expf(lrelu(scs[s1 * 4 + hl] + adv) - mx);
            float p2 = __expf(lrelu(scs[s2 * 4 + hl] + adv) - mx);
            float p3 = __expf(lrelu(scs[s3 * 4 + hl] + adv) - mx);
            dsum += (p0 + p1) + (p2 + p3);
            float2 a0 = __half22float2(*(__half2*)&ra.x);
            float2 a1 = __half22float2(*(__half2*)&ra.y);
            float2 a2 = __half22float2(*(__half2*)&ra.z);
            float2 a3 = __half22float2(*(__half2*)&ra.w);
            float2 b0 = __half22float2(*(__half2*)&rb.x);
            float2 b1 = __half22float2(*(__half2*)&rb.y);
            float2 b2 = __half22float2(*(__half2*)&rb.z);
            float2 b3 = __half22float2(*(__half2*)&rb.w);
            float2 c0 = __half22float2(*(__half2*)&rc.x);
            float2 c1 = __half22float2(*(__half2*)&rc.y);
            float2 c2 = __half22float2(*(__half2*)&rc.z);
            float2 c3 = __half22float2(*(__half2*)&rc.w);
            float2 d0 = __half22float2(*(__half2*)&rd.x);
            float2 d1 = __half22float2(*(__half2*)&rd.y);
            float2 d2 = __half22float2(*(__half2*)&rd.z);
            float2 d3 = __half22float2(*(__half2*)&rd.w);
            acc[0] += (p0 * a0.x + p1 * b0.x) + (p2 * c0.x + p3 * d0.x);
            acc[1] += (p0 * a0.y + p1 * b0.y) + (p2 * c0.y + p3 * d0.y);
            acc[2] += (p0 * a1.x + p1 * b1.x) + (p2 * c1.x + p3 * d1.x);
            acc[3] += (p0 * a1.y + p1 * b1.y) + (p2 * c1.y + p3 * d1.y);
            acc[4] += (p0 * a2.x + p1 * b2.x) + (p2 * c2.x + p3 * d2.x);
            acc[5] += (p0 * a2.y + p1 * b2.y) + (p2 * c2.y + p3 * d2.y);
            acc[6] += (p0 * a3.x + p1 * b3.x) + (p2 * c3.x + p3 * d3.x);
            acc[7] += (p0 * a3.y + p1 * b3.y) + (p2 * c3.y + p3 * d3.y);
        }
        for (; k < r1; k++) {
            int s0 = lst[k];
            uint4 ra = *(const uint4*)(X + (size_t)s0 * FDIM + ch0);
            float p0 = __expf(lrelu(scs[s0 * 4 + hl] + adv) - mx);
            dsum += p0;
            float2 a0 = __half22float2(*(__half2*)&ra.x);
            float2 a1 = __half22float2(*(__half2*)&ra.y);
            float2 a2 = __half22float2(*(__half2*)&ra.z);
            float2 a3 = __half22float2(*(__half2*)&ra.w);
            acc[0] += p0 * a0.x;
            acc[1] += p0 * a0.y;
            acc[2] += p0 * a1.x;
            acc[3] += p0 * a1.y;
            acc[4] += p0 * a2.x;
            acc[5] += p0 * a2.y;
            acc[6] += p0 * a3.x;
            acc[7] += p0 * a3.y;
        }
    }

    float inv = 1.f / (dsum + 1e-16f);
    float ov[8];
#pragma unroll
    for (int j = 0; j < 8; j++) {
        int ch = ch0 + j;
        ov[j] = fmaxf(fmaf(acc[j] * inv, bnA[ch], bnB[ch]), 0.f);
    }

    if (MODE == 0) {
        uint4 hv;
        *(__half2*)&hv.x = __floats2half2_rn(ov[0], ov[1]);
        *(__half2*)&hv.y = __floats2half2_rn(ov[2], ov[3]);
        *(__half2*)&hv.z = __floats2half2_rn(ov[4], ov[5]);
        *(__half2*)&hv.w = __floats2half2_rn(ov[6], ov[7]);
        *(uint4*)(g_A16 + (size_t)n * FDIM + ch0) = hv;
    } else {
        float m2 = ov[0];
#pragma unroll
        for (int j = 1; j < 8; j++) m2 = fmaxf(m2, ov[j]);
#pragma unroll
        for (int off = 16; off > 0; off >>= 1) m2 = fmaxf(m2, __shfl_xor_sync(0xffffffffu, m2, off));
        float se = 0.f;
#pragma unroll
        for (int j = 0; j < 8; j++) se += __expf(ov[j] - m2);
#pragma unroll
        for (int off = 16; off > 0; off >>= 1) se += __shfl_xor_sync(0xffffffffu, se, off);
        float lse = m2 + logf(se);
        float4* op = (float4*)(OUT + (size_t)n * FDIM + ch0);
        op[0] = make_float4(ov[0] - lse, ov[1] - lse, ov[2] - lse, ov[3] - lse);
        op[1] = make_float4(ov[4] - lse, ov[5] - lse, ov[6] - lse, ov[7] - lse);
    }
}

// ---------------- launch ----------------
extern "C" void kernel_launch(void* const* d_in, const int* in_sizes, int n_in,
                              void* d_out, int out_size) {
    const float* x    = (const float*)d_in[0];
    const int*   ei   = (const int*)d_in[1];
    const float* W1   = (const float*)d_in[2];
    const float* as1  = (const float*)d_in[3];
    const float* ad1  = (const float*)d_in[4];
    const float* b1   = (const float*)d_in[5];
    const float* gam1 = (const float*)d_in[6];
    const float* be1  = (const float*)d_in[7];
    const float* m1   = (const float*)d_in[8];
    const float* v1   = (const float*)d_in[9];
    const float* W2   = (const float*)d_in[10];
    const float* as2  = (const float*)d_in[11];
    const float* ad2  = (const float*)d_in[12];
    const float* b2   = (const float*)d_in[13];
    const float* gam2 = (const float*)d_in[14];
    const float* be2  = (const float*)d_in[15];
    const float* m2   = (const float*)d_in[16];
    const float* v2   = (const float*)d_in[17];
    float* out = (float*)d_out;

    __half *A16, *B1, *B2, *bufH2;
    uint8_t *bufH8;
    float *bnA, *bnB, *gmax, *sc1s, *sc1d, *sc2s, *sc2d;
    cudaGetSymbolAddress((void**)&A16, g_A16);
    cudaGetSymbolAddress((void**)&B1, g_B16_1);
    cudaGetSymbolAddress((void**)&B2, g_B16_2);
    cudaGetSymbolAddress((void**)&bufH8, g_bufH8);
    cudaGetSymbolAddress((void**)&bufH2, g_bufH2);
    cudaGetSymbolAddress((void**)&bnA, g_bnA);
    cudaGetSymbolAddress((void**)&bnB, g_bnB);
    cudaGetSymbolAddress((void**)&gmax, g_gmax);
    cudaGetSymbolAddress((void**)&sc1s, g_asrcv);
    cudaGetSymbolAddress((void**)&sc1d, g_adstv);
    cudaGetSymbolAddress((void**)&sc2s, g_asrcv2);
    cudaGetSymbolAddress((void**)&sc2d, g_adstv2);

    static cudaStream_t s2 = nullptr;
    static cudaEvent_t evF = nullptr, evJ = nullptr;
    if (s2 == nullptr) {
        cudaStreamCreateWithFlags(&s2, cudaStreamNonBlocking);
        cudaEventCreateWithFlags(&evF, cudaEventDisableTiming);
        cudaEventCreateWithFlags(&evJ, cudaEventDisableTiming);
    }

    const int GSMEM = 2 * GSTAGE;  // 37888
    cudaFuncSetAttribute(k_gemm_mma<0>, cudaFuncAttributeMaxDynamicSharedMemorySize, GSMEM);
    cudaFuncSetAttribute(k_gemm_mma<1>, cudaFuncAttributeMaxDynamicSharedMemorySize, GSMEM);

    dim3 ggrid(2, 391);

    // ---- fork ----
    cudaEventRecord(evF, 0);
    cudaStreamWaitEvent(s2, evF, 0);

    // branch A (main): fused prep (A16, W1, W2, BN) + layer-1 GEMM
    k_prepAll<<<PREPA_BLKS + 128 + 256 + 1, 256>>>(x, W1, B1, W2, B2,
                                                   b1, gam1, be1, m1, v1,
                                                   b2, gam2, be2, m2, v2);
    // branch B (s2): pure CSR build
    k_count<<<(NEDGES + 255) / 256, 256, 0, s2>>>(ei);
    k_alloc<<<(NNODES + 255) / 256, 256, 0, s2>>>();
    k_fill<<<(NEDGES + 255) / 256, 256, 0, s2>>>(ei);
    k_sort<<<(NNODES + 255) / 256, 256, 0, s2>>>();
    cudaEventRecord(evJ, s2);

    k_gemm_mma<1><<<ggrid, 256, GSMEM>>>(A16, B1, bufH8, 128, as1, ad1, sc1s, sc1d, gmax);

    // ---- join ----
    cudaStreamWaitEvent(0, evJ, 0);

    // layer 1 aggregation (fp8 gather)
    k_agg<0><<<(NNODES + 7) / 8, 256>>>(bufH8, sc1s, sc1d, bnA, bnB, gmax, nullptr);

    // layer 2
    k_gemm_mma<0><<<ggrid, 256, GSMEM>>>(A16, B2, bufH2, 256, as2, ad2, sc2s, sc2d, gmax + 4);
    k_agg<1><<<(NNODES + 7) / 8, 256>>>(bufH2, sc2s, sc2d, bnA + 256, bnB + 256, gmax + 4, out);
}